// round 6
// baseline (speedup 1.0000x reference)
#include <cuda_runtime.h>

#define HD      768
#define SEQ     256
#define BATCH   4
#define ROWS    1024
#define NP      54
#define THRESH  0.5f
#define ROWOUT  (SEQ * NP)          // 13824
#define OUT_F4  (ROWS * ROWOUT / 4) // 3,538,944 float4
#define CROWS   (ROWS * HD)         // 786432 floats per split buffer

typedef unsigned long long u64;

// Scratch (device globals — no allocation allowed)
__device__ float g_c[3 * CROWS];         // split-K partials of x @ W1s^T (9.4 MB)
__device__ float g_hab[ROWS * 2 * HD];   // [row][ha | hb], candidate rows only
__device__ int   g_cand[ROWS];

__device__ __forceinline__ void fma2(u64& d, u64 a, u64 b) {
    asm("fma.rn.f32x2 %0, %1, %2, %0;" : "+l"(d) : "l"(a), "l"(b));
}
__device__ __forceinline__ u64 dup2(float a) {
    u64 r; asm("mov.b64 %0, {%1, %1};" : "=l"(r) : "f"(a)); return r;
}
__device__ __forceinline__ void unpack2(float& lo, float& hi, u64 v) {
    asm("mov.b64 {%0, %1}, %2;" : "=f"(lo), "=f"(hi) : "l"(v));
}

// ---------------------------------------------------------------------------
// GEMM: partial c = x[:, ks:ks+256] @ W1s[:, ks:ks+256]^T  -> g_c[split]
// BM=128, BN=64, BK=16, 256 threads, 8m x 4n per thread, m-pair packed FFMA2.
// Also trickles the 56.6MB output zero-fill through the k-loop.
// ---------------------------------------------------------------------------
#define BM 128
#define BN 64
#define BK 16
#define KSPLIT 256
#define LDA 132
#define LDB 68

__global__ void __launch_bounds__(256, 2) gemm_kernel(
    const float* __restrict__ X,
    const float* __restrict__ W1s,
    float* __restrict__ out)
{
    __shared__ float As[2][BK * LDA];
    __shared__ float Bs[2][BK * LDB];

    const int tid = threadIdx.x;
    const int n0 = blockIdx.x * BN;
    const int m0 = blockIdx.y * BM;
    const int ks = blockIdx.z * KSPLIT;
    const int ty = tid >> 4;          // 0..15 : rows ty*8..+7
    const int tx = tid & 15;          // 0..15 : cols tx*4..+3

    // zero-fill region for this CTA: 12288 float4 (48 per thread)
    const int ctaid = blockIdx.z * 96 + blockIdx.y * 12 + blockIdx.x;  // 0..287
    float4* o4 = (float4*)out + ctaid * 12288 + tid;

    // loader mapping
    const int am  = tid >> 2;         // 0..63 (A rows am, am+64)
    const int akq = (tid & 3) * 4;    // k quad
    const int bn  = tid & 63;         // B row
    const int bkq = (tid >> 6) * 4;   // k quad

    const float* gA0 = X + (m0 + am) * HD + ks + akq;
    const float* gA1 = gA0 + 64 * HD;
    const float* gB  = W1s + (n0 + bn) * HD + ks + bkq;

    u64 acc[4][4];   // acc[j][ip] : cols tx*4+j, row-pairs (2ip, 2ip+1)
    #pragma unroll
    for (int j = 0; j < 4; j++)
        #pragma unroll
        for (int ip = 0; ip < 4; ip++) acc[j][ip] = 0ull;

    float4 ra0, ra1, rb;

    // prologue: load tile0, store buf0, load tile1
    ra0 = *(const float4*)gA0;
    ra1 = *(const float4*)gA1;
    rb  = *(const float4*)gB;
    {
        As[0][(akq+0)*LDA + am]      = ra0.x;  As[0][(akq+1)*LDA + am]      = ra0.y;
        As[0][(akq+2)*LDA + am]      = ra0.z;  As[0][(akq+3)*LDA + am]      = ra0.w;
        As[0][(akq+0)*LDA + am + 64] = ra1.x;  As[0][(akq+1)*LDA + am + 64] = ra1.y;
        As[0][(akq+2)*LDA + am + 64] = ra1.z;  As[0][(akq+3)*LDA + am + 64] = ra1.w;
        Bs[0][(bkq+0)*LDB + bn] = rb.x;  Bs[0][(bkq+1)*LDB + bn] = rb.y;
        Bs[0][(bkq+2)*LDB + bn] = rb.z;  Bs[0][(bkq+3)*LDB + bn] = rb.w;
    }
    ra0 = *(const float4*)(gA0 + BK);
    ra1 = *(const float4*)(gA1 + BK);
    rb  = *(const float4*)(gB  + BK);

    const int NITER = KSPLIT / BK;   // 16
    const float4 z4 = make_float4(0.f, 0.f, 0.f, 0.f);

    for (int it = 0; it < NITER; it++) {
        __syncthreads();
        const int cb = it & 1;

        // trickle 3 zero stores per iteration (48 total per thread)
        o4[(it * 3 + 0) * 256] = z4;
        o4[(it * 3 + 1) * 256] = z4;
        o4[(it * 3 + 2) * 256] = z4;

        #pragma unroll
        for (int k = 0; k < BK; k++) {
            ulonglong2 a01 = *(const ulonglong2*)&As[cb][k * LDA + ty * 8];
            ulonglong2 a23 = *(const ulonglong2*)&As[cb][k * LDA + ty * 8 + 4];
            float4 bf = *(const float4*)&Bs[cb][k * LDB + tx * 4];
            u64 ap[4] = {a01.x, a01.y, a23.x, a23.y};
            u64 bd[4] = {dup2(bf.x), dup2(bf.y), dup2(bf.z), dup2(bf.w)};
            #pragma unroll
            for (int j = 0; j < 4; j++)
                #pragma unroll
                for (int ip = 0; ip < 4; ip++)
                    fma2(acc[j][ip], ap[ip], bd[j]);
        }

        if (it + 1 < NITER) {
            const int sb = (it + 1) & 1;
            As[sb][(akq+0)*LDA + am]      = ra0.x;  As[sb][(akq+1)*LDA + am]      = ra0.y;
            As[sb][(akq+2)*LDA + am]      = ra0.z;  As[sb][(akq+3)*LDA + am]      = ra0.w;
            As[sb][(akq+0)*LDA + am + 64] = ra1.x;  As[sb][(akq+1)*LDA + am + 64] = ra1.y;
            As[sb][(akq+2)*LDA + am + 64] = ra1.z;  As[sb][(akq+3)*LDA + am + 64] = ra1.w;
            Bs[sb][(bkq+0)*LDB + bn] = rb.x;  Bs[sb][(bkq+1)*LDB + bn] = rb.y;
            Bs[sb][(bkq+2)*LDB + bn] = rb.z;  Bs[sb][(bkq+3)*LDB + bn] = rb.w;
            if (it + 2 < NITER) {
                int ko = (it + 2) * BK;
                ra0 = *(const float4*)(gA0 + ko);
                ra1 = *(const float4*)(gA1 + ko);
                rb  = *(const float4*)(gB  + ko);
            }
        }
    }

    // epilogue: write raw partials
    float cv[8][4];
    #pragma unroll
    for (int j = 0; j < 4; j++)
        #pragma unroll
        for (int ip = 0; ip < 4; ip++)
            unpack2(cv[2*ip][j], cv[2*ip+1][j], acc[j][ip]);

    float* cb = g_c + blockIdx.z * CROWS;
    #pragma unroll
    for (int i = 0; i < 8; i++) {
        int m = m0 + ty * 8 + i;
        *(float4*)&cb[m * HD + n0 + tx * 4] =
            make_float4(cv[i][0], cv[i][1], cv[i][2], cv[i][3]);
    }
}

// ---------------------------------------------------------------------------
// CAND: warp per row: span = sum_n relu(c0+c1+c2 + b1s)*W2s[0] + b2s[0]
// ---------------------------------------------------------------------------
__global__ void __launch_bounds__(256) cand_kernel(
    const float* __restrict__ b1s,
    const float* __restrict__ W2s,
    const float* __restrict__ b2s)
{
    const int row  = (blockIdx.x * 256 + threadIdx.x) >> 5;  // 0..1023
    const int lane = threadIdx.x & 31;
    float s = 0.f;
    #pragma unroll
    for (int t = 0; t < HD / 32; t++) {
        int k = lane + 32 * t;
        float c = g_c[row * HD + k] + g_c[CROWS + row * HD + k]
                + g_c[2 * CROWS + row * HD + k];
        s += fmaxf(c + b1s[k], 0.f) * W2s[k];
    }
    #pragma unroll
    for (int o = 16; o > 0; o >>= 1)
        s += __shfl_xor_sync(0xffffffffu, s, o);
    if (lane == 0)
        g_cand[row] = (s + b2s[0]) > THRESH ? 1 : 0;
}

// ---------------------------------------------------------------------------
// HAB: ha/hb for candidate rows. item = (row, 128-col chunk), grid-stride.
// ---------------------------------------------------------------------------
__global__ void __launch_bounds__(256) hab_kernel(
    const float* __restrict__ X,
    const float* __restrict__ Wp1)
{
    __shared__ float xs[HD];
    const int tid  = threadIdx.x;
    const int warp = tid >> 5;
    const int lane = tid & 31;

    for (int item = blockIdx.x; item < ROWS * 12; item += gridDim.x) {
        int row = item / 12;
        int chunk = item - row * 12;
        if (!g_cand[row]) continue;                    // block-uniform
        __syncthreads();
        for (int k = tid; k < HD; k += 256) xs[k] = X[row * HD + k];
        __syncthreads();
        #pragma unroll 4
        for (int cc = 0; cc < 16; cc++) {
            int c = chunk * 128 + warp * 16 + cc;      // 0..1535
            const float* wrow = (c < HD) ? (Wp1 + (size_t)c * (2 * HD))
                                         : (Wp1 + (size_t)(c - HD) * (2 * HD) + HD);
            float s = 0.f;
            #pragma unroll
            for (int t = 0; t < HD / 32; t++)
                s += xs[lane + 32 * t] * __ldg(&wrow[lane + 32 * t]);
            #pragma unroll
            for (int o = 16; o > 0; o >>= 1)
                s += __shfl_xor_sync(0xffffffffu, s, o);
            if (lane == 0) g_hab[(size_t)row * (2 * HD) + c] = s;
        }
    }
}

// ---------------------------------------------------------------------------
// PAIR: block = (rowi, j-slice of 64). Non-candidate rowi exits immediately.
// ---------------------------------------------------------------------------
__global__ void __launch_bounds__(256) pair_kernel(
    const float* __restrict__ bp1,
    const float* __restrict__ Wp2,
    const float* __restrict__ bp2,
    float* __restrict__ out)
{
    const int rowi = blockIdx.x >> 2;
    const int jsl  = blockIdx.x & 3;
    if (!g_cand[rowi]) return;

    __shared__ float vsi[HD];
    __shared__ float v[HD];
    __shared__ int   sj[64];

    const int b = rowi >> 8;
    const int i = rowi & 255;
    const int tid = threadIdx.x;

    if (tid < 64) {
        int j = jsl * 64 + tid;
        sj[tid] = (j != i) && g_cand[(b << 8) | j];
    }
    for (int k = tid; k < HD; k += 256)
        vsi[k] = g_hab[(size_t)rowi * (2 * HD) + k] + bp1[k];
    __syncthreads();

    const int warp = tid >> 5;
    const int lane = tid & 31;
    float* obase = out + (size_t)rowi * ROWOUT;

    for (int jj = 0; jj < 64; jj++) {
        if (!sj[jj]) continue;
        int j = jsl * 64 + jj;
        int rowj = (b << 8) | j;
        for (int k = tid; k < HD; k += 256)
            v[k] = fmaxf(vsi[k] + g_hab[(size_t)rowj * (2 * HD) + HD + k], 0.f);
        __syncthreads();
        for (int p = warp; p < NP; p += 8) {
            float s = 0.f;
            #pragma unroll
            for (int t = 0; t < HD / 32; t++)
                s += v[lane + 32 * t] * __ldg(&Wp2[p * HD + lane + 32 * t]);
            #pragma unroll
            for (int off = 16; off > 0; off >>= 1)
                s += __shfl_xor_sync(0xffffffffu, s, off);
            if (lane == 0) obase[j * NP + p] = s + bp2[p];
        }
        __syncthreads();
    }
}

// ---------------------------------------------------------------------------
extern "C" void kernel_launch(void* const* d_in, const int* in_sizes, int n_in,
                              void* d_out, int out_size)
{
    const float* x   = (const float*)d_in[0];   // [4,256,768]
    const float* W1s = (const float*)d_in[1];   // [768,768]
    const float* b1s = (const float*)d_in[2];   // [768]
    const float* W2s = (const float*)d_in[3];   // [2,768]
    const float* b2s = (const float*)d_in[4];   // [2]
    const float* Wp1 = (const float*)d_in[5];   // [768,1536]
    const float* bp1 = (const float*)d_in[6];   // [768]
    const float* Wp2 = (const float*)d_in[7];   // [54,768]
    const float* bp2 = (const float*)d_in[8];   // [54]
    float* out = (float*)d_out;

    // 1) split-K partial GEMM + fused output zero-fill
    dim3 g1(HD / BN, ROWS / BM, 3);              // (12, 8, 3) = 288 CTAs
    gemm_kernel<<<g1, 256>>>(x, W1s, out);

    // 2) candidate mask (warp per row)
    cand_kernel<<<ROWS / 8, 256>>>(b1s, W2s, b2s);

    // 3) ha/hb for candidate rows
    hab_kernel<<<256, 256>>>(x, Wp1);

    // 4) sparse pair logits
    pair_kernel<<<4096, 256>>>(bp1, Wp2, bp2, out);
}

// round 7
// speedup vs baseline: 1.1988x; 1.1988x over previous
#include <cuda_runtime.h>

#define HD      768
#define SEQ     256
#define BATCH   4
#define ROWS    1024
#define NP      54
#define THRESH  0.5f
#define ROWOUT  (SEQ * NP)          // 13824
#define CROWS   (ROWS * HD)         // 786432 floats per split buffer

typedef unsigned long long u64;

// Scratch (device globals — no allocation allowed)
__device__ float g_c[3 * CROWS];         // split-K partials of x @ W1s^T (9.4 MB)
__device__ float g_hab[ROWS * 2 * HD];   // [row][ha | hb], candidate rows only
__device__ int   g_cand[ROWS];
__device__ int   g_rows[ROWS];
__device__ int   g_pairs[BATCH * SEQ * SEQ];
__device__ int   g_cnt;
__device__ int   g_nrows;

__device__ __forceinline__ void fma2(u64& d, u64 a, u64 b) {
    asm("fma.rn.f32x2 %0, %1, %2, %0;" : "+l"(d) : "l"(a), "l"(b));
}
__device__ __forceinline__ u64 dup2(float a) {
    u64 r; asm("mov.b64 %0, {%1, %1};" : "=l"(r) : "f"(a)); return r;
}
__device__ __forceinline__ void unpack2(float& lo, float& hi, u64 v) {
    asm("mov.b64 {%0, %1}, %2;" : "=f"(lo), "=f"(hi) : "l"(v));
}

// ---------------------------------------------------------------------------
// GEMM: partial c = x[:, ks:ks+256] @ W1s[:, ks:ks+256]^T  -> g_c[split]
// BM=128, BN=64, BK=16, 256 threads, m-pair packed FFMA2, split-K = 3.
// Trickles the 56.6MB output zero-fill through the k-loop.
// ---------------------------------------------------------------------------
#define BM 128
#define BN 64
#define BK 16
#define KSPLIT 256
#define LDA 132
#define LDB 68

__global__ void __launch_bounds__(256, 2) gemm_kernel(
    const float* __restrict__ X,
    const float* __restrict__ W1s,
    float* __restrict__ out)
{
    __shared__ float As[2][BK * LDA];
    __shared__ float Bs[2][BK * LDB];

    const int tid = threadIdx.x;
    const int n0 = blockIdx.x * BN;
    const int m0 = blockIdx.y * BM;
    const int ks = blockIdx.z * KSPLIT;
    const int ty = tid >> 4;
    const int tx = tid & 15;

    const int ctaid = blockIdx.z * 96 + blockIdx.y * 12 + blockIdx.x;  // 0..287
    float4* o4 = (float4*)out + ctaid * 12288 + tid;

    const int am  = tid >> 2;
    const int akq = (tid & 3) * 4;
    const int bn  = tid & 63;
    const int bkq = (tid >> 6) * 4;

    const float* gA0 = X + (m0 + am) * HD + ks + akq;
    const float* gA1 = gA0 + 64 * HD;
    const float* gB  = W1s + (n0 + bn) * HD + ks + bkq;

    u64 acc[4][4];
    #pragma unroll
    for (int j = 0; j < 4; j++)
        #pragma unroll
        for (int ip = 0; ip < 4; ip++) acc[j][ip] = 0ull;

    float4 ra0, ra1, rb;

    ra0 = *(const float4*)gA0;
    ra1 = *(const float4*)gA1;
    rb  = *(const float4*)gB;
    {
        As[0][(akq+0)*LDA + am]      = ra0.x;  As[0][(akq+1)*LDA + am]      = ra0.y;
        As[0][(akq+2)*LDA + am]      = ra0.z;  As[0][(akq+3)*LDA + am]      = ra0.w;
        As[0][(akq+0)*LDA + am + 64] = ra1.x;  As[0][(akq+1)*LDA + am + 64] = ra1.y;
        As[0][(akq+2)*LDA + am + 64] = ra1.z;  As[0][(akq+3)*LDA + am + 64] = ra1.w;
        Bs[0][(bkq+0)*LDB + bn] = rb.x;  Bs[0][(bkq+1)*LDB + bn] = rb.y;
        Bs[0][(bkq+2)*LDB + bn] = rb.z;  Bs[0][(bkq+3)*LDB + bn] = rb.w;
    }
    ra0 = *(const float4*)(gA0 + BK);
    ra1 = *(const float4*)(gA1 + BK);
    rb  = *(const float4*)(gB  + BK);

    const int NITER = KSPLIT / BK;   // 16
    const float4 z4 = make_float4(0.f, 0.f, 0.f, 0.f);

    for (int it = 0; it < NITER; it++) {
        __syncthreads();
        const int cb = it & 1;

        o4[(it * 3 + 0) * 256] = z4;
        o4[(it * 3 + 1) * 256] = z4;
        o4[(it * 3 + 2) * 256] = z4;

        #pragma unroll
        for (int k = 0; k < BK; k++) {
            ulonglong2 a01 = *(const ulonglong2*)&As[cb][k * LDA + ty * 8];
            ulonglong2 a23 = *(const ulonglong2*)&As[cb][k * LDA + ty * 8 + 4];
            float4 bf = *(const float4*)&Bs[cb][k * LDB + tx * 4];
            u64 ap[4] = {a01.x, a01.y, a23.x, a23.y};
            u64 bd[4] = {dup2(bf.x), dup2(bf.y), dup2(bf.z), dup2(bf.w)};
            #pragma unroll
            for (int j = 0; j < 4; j++)
                #pragma unroll
                for (int ip = 0; ip < 4; ip++)
                    fma2(acc[j][ip], ap[ip], bd[j]);
        }

        if (it + 1 < NITER) {
            const int sb = (it + 1) & 1;
            As[sb][(akq+0)*LDA + am]      = ra0.x;  As[sb][(akq+1)*LDA + am]      = ra0.y;
            As[sb][(akq+2)*LDA + am]      = ra0.z;  As[sb][(akq+3)*LDA + am]      = ra0.w;
            As[sb][(akq+0)*LDA + am + 64] = ra1.x;  As[sb][(akq+1)*LDA + am + 64] = ra1.y;
            As[sb][(akq+2)*LDA + am + 64] = ra1.z;  As[sb][(akq+3)*LDA + am + 64] = ra1.w;
            Bs[sb][(bkq+0)*LDB + bn] = rb.x;  Bs[sb][(bkq+1)*LDB + bn] = rb.y;
            Bs[sb][(bkq+2)*LDB + bn] = rb.z;  Bs[sb][(bkq+3)*LDB + bn] = rb.w;
            if (it + 2 < NITER) {
                int ko = (it + 2) * BK;
                ra0 = *(const float4*)(gA0 + ko);
                ra1 = *(const float4*)(gA1 + ko);
                rb  = *(const float4*)(gB  + ko);
            }
        }
    }

    float cv[8][4];
    #pragma unroll
    for (int j = 0; j < 4; j++)
        #pragma unroll
        for (int ip = 0; ip < 4; ip++)
            unpack2(cv[2*ip][j], cv[2*ip+1][j], acc[j][ip]);

    float* cb = g_c + blockIdx.z * CROWS;
    #pragma unroll
    for (int i = 0; i < 8; i++) {
        int m = m0 + ty * 8 + i;
        *(float4*)&cb[m * HD + n0 + tx * 4] =
            make_float4(cv[i][0], cv[i][1], cv[i][2], cv[i][3]);
    }
}

// ---------------------------------------------------------------------------
// CAND: warp per row: span = sum_n relu(c0+c1+c2 + b1s)*W2s[0] + b2s[0]
// Also resets the compaction counters (separate later launch consumes them).
// ---------------------------------------------------------------------------
__global__ void __launch_bounds__(256) cand_kernel(
    const float* __restrict__ b1s,
    const float* __restrict__ W2s,
    const float* __restrict__ b2s)
{
    if (blockIdx.x == 0 && threadIdx.x == 0) { g_cnt = 0; g_nrows = 0; }
    const int row  = (blockIdx.x * 256 + threadIdx.x) >> 5;
    const int lane = threadIdx.x & 31;
    float s = 0.f;
    #pragma unroll
    for (int t = 0; t < HD / 32; t++) {
        int k = lane + 32 * t;
        float c = g_c[row * HD + k] + g_c[CROWS + row * HD + k]
                + g_c[2 * CROWS + row * HD + k];
        s += fmaxf(c + b1s[k], 0.f) * W2s[k];
    }
    #pragma unroll
    for (int o = 16; o > 0; o >>= 1)
        s += __shfl_xor_sync(0xffffffffu, s, o);
    if (lane == 0)
        g_cand[row] = (s + b2s[0]) > THRESH ? 1 : 0;
}

// ---------------------------------------------------------------------------
// COMPACT: one block per batch. Builds row list + pair list.
// ---------------------------------------------------------------------------
__global__ void __launch_bounds__(SEQ) compact_kernel()
{
    __shared__ int fc[SEQ];
    const int b = blockIdx.x;
    const int t = threadIdx.x;           // = i within batch
    fc[t] = g_cand[b * SEQ + t];
    __syncthreads();
    if (fc[t]) {
        int r = atomicAdd(&g_nrows, 1);
        g_rows[r] = b * SEQ + t;
        for (int j = 0; j < SEQ; j++) {
            if (fc[j] && j != t) {
                int p = atomicAdd(&g_cnt, 1);
                g_pairs[p] = (b * SEQ + t) * SEQ + j;   // rowi*256 + j
            }
        }
    }
}

// ---------------------------------------------------------------------------
// HAB: ha/hb for candidate rows only (list-driven), item = (row_slot, chunk).
// ---------------------------------------------------------------------------
__global__ void __launch_bounds__(256) hab_kernel(
    const float* __restrict__ X,
    const float* __restrict__ Wp1)
{
    __shared__ float xs[HD];
    const int tid  = threadIdx.x;
    const int warp = tid >> 5;
    const int lane = tid & 31;
    const int total = g_nrows * 12;

    for (int item = blockIdx.x; item < total; item += gridDim.x) {
        int rs = item / 12;
        int chunk = item - rs * 12;
        int row = g_rows[rs];
        __syncthreads();
        for (int k = tid; k < HD; k += 256) xs[k] = X[row * HD + k];
        __syncthreads();
        #pragma unroll 4
        for (int cc = 0; cc < 16; cc++) {
            int c = chunk * 128 + warp * 16 + cc;      // 0..1535
            const float* wrow = (c < HD) ? (Wp1 + (size_t)c * (2 * HD))
                                         : (Wp1 + (size_t)(c - HD) * (2 * HD) + HD);
            float s = 0.f;
            #pragma unroll
            for (int t = 0; t < HD / 32; t++)
                s += xs[lane + 32 * t] * __ldg(&wrow[lane + 32 * t]);
            #pragma unroll
            for (int o = 16; o > 0; o >>= 1)
                s += __shfl_xor_sync(0xffffffffu, s, o);
            if (lane == 0) g_hab[(size_t)row * (2 * HD) + c] = s;
        }
    }
}

// ---------------------------------------------------------------------------
// PAIR: one block per valid pair (grid-stride over g_cnt).
// out[b,i,j,:] = relu(ha_i + hb_j + bp1) @ Wp2^T + bp2
// ---------------------------------------------------------------------------
__global__ void __launch_bounds__(256) pair_kernel(
    const float* __restrict__ bp1,
    const float* __restrict__ Wp2,
    const float* __restrict__ bp2,
    float* __restrict__ out)
{
    __shared__ float v[HD];
    const int tid  = threadIdx.x;
    const int warp = tid >> 5;
    const int lane = tid & 31;
    const int cnt  = g_cnt;

    for (int p = blockIdx.x; p < cnt; p += gridDim.x) {
        int code = g_pairs[p];
        int rowi = code >> 8;
        int j    = code & 255;
        int rowj = (rowi & ~255) | j;

        __syncthreads();
        for (int k = tid; k < HD; k += 256)
            v[k] = fmaxf(g_hab[(size_t)rowi * (2 * HD) + k] +
                         g_hab[(size_t)rowj * (2 * HD) + HD + k] + bp1[k], 0.f);
        __syncthreads();

        float* o = out + (size_t)code * NP;    // code == (rowi*SEQ + j)
        for (int pp = warp; pp < NP; pp += 8) {
            float s = 0.f;
            #pragma unroll
            for (int t = 0; t < HD / 32; t++)
                s += v[lane + 32 * t] * __ldg(&Wp2[pp * HD + lane + 32 * t]);
            #pragma unroll
            for (int off = 16; off > 0; off >>= 1)
                s += __shfl_xor_sync(0xffffffffu, s, off);
            if (lane == 0) o[pp] = s + bp2[pp];
        }
    }
}

// ---------------------------------------------------------------------------
extern "C" void kernel_launch(void* const* d_in, const int* in_sizes, int n_in,
                              void* d_out, int out_size)
{
    const float* x   = (const float*)d_in[0];
    const float* W1s = (const float*)d_in[1];
    const float* b1s = (const float*)d_in[2];
    const float* W2s = (const float*)d_in[3];
    const float* b2s = (const float*)d_in[4];
    const float* Wp1 = (const float*)d_in[5];
    const float* bp1 = (const float*)d_in[6];
    const float* Wp2 = (const float*)d_in[7];
    const float* bp2 = (const float*)d_in[8];
    float* out = (float*)d_out;

    // 1) split-K partial GEMM + fused output zero-fill
    dim3 g1(HD / BN, ROWS / BM, 3);              // 288 CTAs, single wave
    gemm_kernel<<<g1, 256>>>(x, W1s, out);

    // 2) candidate mask (warp per row) + counter reset
    cand_kernel<<<ROWS / 8, 256>>>(b1s, W2s, b2s);

    // 3) build row + pair lists
    compact_kernel<<<BATCH, SEQ>>>();

    // 4) ha/hb for candidate rows (list-driven)
    hab_kernel<<<512, 256>>>(x, Wp1);

    // 5) one block per valid pair
    pair_kernel<<<1024, 256>>>(bp1, Wp2, bp2, out);
}

// round 8
// speedup vs baseline: 1.5627x; 1.3036x over previous
#include <cuda_runtime.h>

#define HD      768
#define SEQ     256
#define BATCH   4
#define ROWS    1024
#define NP      54
#define THRESH  0.5f
#define ROWOUT  (SEQ * NP)          // 13824
#define CROWS   (ROWS * HD)         // 786432 floats per split buffer

typedef unsigned long long u64;

// Scratch (device globals — no allocation allowed)
__device__ float g_c[3 * CROWS];         // split-K partials of x @ W1s^T (9.4 MB)
__device__ float g_hab[ROWS * 2 * HD];   // [row][ha | hb], candidate rows only
__device__ int   g_cand[ROWS];
__device__ int   g_rows[ROWS];
__device__ int   g_pairs[BATCH * SEQ * SEQ];
__device__ int   g_cnt;
__device__ int   g_nrows;

__device__ __forceinline__ void fma2(u64& d, u64 a, u64 b) {
    asm("fma.rn.f32x2 %0, %1, %2, %0;" : "+l"(d) : "l"(a), "l"(b));
}
__device__ __forceinline__ u64 dup2(float a) {
    u64 r; asm("mov.b64 %0, {%1, %1};" : "=l"(r) : "f"(a)); return r;
}
__device__ __forceinline__ void unpack2(float& lo, float& hi, u64 v) {
    asm("mov.b64 {%0, %1}, %2;" : "=f"(lo), "=f"(hi) : "l"(v));
}

// ---------------------------------------------------------------------------
// GEMM: partial c = x[:, ks:ks+256] @ W1s[:, ks:ks+256]^T  -> g_c[split]
// BM=128, BN=64, BK=16, 256 threads, m-pair packed FFMA2, split-K = 3.
// Trickles the 56.6MB output zero-fill through the k-loop.
// ---------------------------------------------------------------------------
#define BM 128
#define BN 64
#define BK 16
#define KSPLIT 256
#define LDA 132
#define LDB 68

__global__ void __launch_bounds__(256, 2) gemm_kernel(
    const float* __restrict__ X,
    const float* __restrict__ W1s,
    float* __restrict__ out)
{
    __shared__ float As[2][BK * LDA];
    __shared__ float Bs[2][BK * LDB];

    const int tid = threadIdx.x;
    const int n0 = blockIdx.x * BN;
    const int m0 = blockIdx.y * BM;
    const int ks = blockIdx.z * KSPLIT;
    const int ty = tid >> 4;
    const int tx = tid & 15;

    const int ctaid = blockIdx.z * 96 + blockIdx.y * 12 + blockIdx.x;  // 0..287
    float4* o4 = (float4*)out + ctaid * 12288 + tid;

    const int am  = tid >> 2;
    const int akq = (tid & 3) * 4;
    const int bn  = tid & 63;
    const int bkq = (tid >> 6) * 4;

    const float* gA0 = X + (m0 + am) * HD + ks + akq;
    const float* gA1 = gA0 + 64 * HD;
    const float* gB  = W1s + (n0 + bn) * HD + ks + bkq;

    u64 acc[4][4];
    #pragma unroll
    for (int j = 0; j < 4; j++)
        #pragma unroll
        for (int ip = 0; ip < 4; ip++) acc[j][ip] = 0ull;

    float4 ra0, ra1, rb;

    ra0 = *(const float4*)gA0;
    ra1 = *(const float4*)gA1;
    rb  = *(const float4*)gB;
    {
        As[0][(akq+0)*LDA + am]      = ra0.x;  As[0][(akq+1)*LDA + am]      = ra0.y;
        As[0][(akq+2)*LDA + am]      = ra0.z;  As[0][(akq+3)*LDA + am]      = ra0.w;
        As[0][(akq+0)*LDA + am + 64] = ra1.x;  As[0][(akq+1)*LDA + am + 64] = ra1.y;
        As[0][(akq+2)*LDA + am + 64] = ra1.z;  As[0][(akq+3)*LDA + am + 64] = ra1.w;
        Bs[0][(bkq+0)*LDB + bn] = rb.x;  Bs[0][(bkq+1)*LDB + bn] = rb.y;
        Bs[0][(bkq+2)*LDB + bn] = rb.z;  Bs[0][(bkq+3)*LDB + bn] = rb.w;
    }
    ra0 = *(const float4*)(gA0 + BK);
    ra1 = *(const float4*)(gA1 + BK);
    rb  = *(const float4*)(gB  + BK);

    const int NITER = KSPLIT / BK;   // 16
    const float4 z4 = make_float4(0.f, 0.f, 0.f, 0.f);

    for (int it = 0; it < NITER; it++) {
        __syncthreads();
        const int cb = it & 1;

        o4[(it * 3 + 0) * 256] = z4;
        o4[(it * 3 + 1) * 256] = z4;
        o4[(it * 3 + 2) * 256] = z4;

        #pragma unroll
        for (int k = 0; k < BK; k++) {
            ulonglong2 a01 = *(const ulonglong2*)&As[cb][k * LDA + ty * 8];
            ulonglong2 a23 = *(const ulonglong2*)&As[cb][k * LDA + ty * 8 + 4];
            float4 bf = *(const float4*)&Bs[cb][k * LDB + tx * 4];
            u64 ap[4] = {a01.x, a01.y, a23.x, a23.y};
            u64 bd[4] = {dup2(bf.x), dup2(bf.y), dup2(bf.z), dup2(bf.w)};
            #pragma unroll
            for (int j = 0; j < 4; j++)
                #pragma unroll
                for (int ip = 0; ip < 4; ip++)
                    fma2(acc[j][ip], ap[ip], bd[j]);
        }

        if (it + 1 < NITER) {
            const int sb = (it + 1) & 1;
            As[sb][(akq+0)*LDA + am]      = ra0.x;  As[sb][(akq+1)*LDA + am]      = ra0.y;
            As[sb][(akq+2)*LDA + am]      = ra0.z;  As[sb][(akq+3)*LDA + am]      = ra0.w;
            As[sb][(akq+0)*LDA + am + 64] = ra1.x;  As[sb][(akq+1)*LDA + am + 64] = ra1.y;
            As[sb][(akq+2)*LDA + am + 64] = ra1.z;  As[sb][(akq+3)*LDA + am + 64] = ra1.w;
            Bs[sb][(bkq+0)*LDB + bn] = rb.x;  Bs[sb][(bkq+1)*LDB + bn] = rb.y;
            Bs[sb][(bkq+2)*LDB + bn] = rb.z;  Bs[sb][(bkq+3)*LDB + bn] = rb.w;
            if (it + 2 < NITER) {
                int ko = (it + 2) * BK;
                ra0 = *(const float4*)(gA0 + ko);
                ra1 = *(const float4*)(gA1 + ko);
                rb  = *(const float4*)(gB  + ko);
            }
        }
    }

    float cv[8][4];
    #pragma unroll
    for (int j = 0; j < 4; j++)
        #pragma unroll
        for (int ip = 0; ip < 4; ip++)
            unpack2(cv[2*ip][j], cv[2*ip+1][j], acc[j][ip]);

    float* cb = g_c + blockIdx.z * CROWS;
    #pragma unroll
    for (int i = 0; i < 8; i++) {
        int m = m0 + ty * 8 + i;
        *(float4*)&cb[m * HD + n0 + tx * 4] =
            make_float4(cv[i][0], cv[i][1], cv[i][2], cv[i][3]);
    }
}

// ---------------------------------------------------------------------------
// CAND: warp per row: span = sum_n relu(c0+c1+c2 + b1s)*W2s[0] + b2s[0]
// Also resets the compaction counters.
// ---------------------------------------------------------------------------
__global__ void __launch_bounds__(256) cand_kernel(
    const float* __restrict__ b1s,
    const float* __restrict__ W2s,
    const float* __restrict__ b2s)
{
    if (blockIdx.x == 0 && threadIdx.x == 0) { g_cnt = 0; g_nrows = 0; }
    const int row  = (blockIdx.x * 256 + threadIdx.x) >> 5;
    const int lane = threadIdx.x & 31;
    float s = 0.f;
    #pragma unroll
    for (int t = 0; t < HD / 32; t++) {
        int k = lane + 32 * t;
        float c = g_c[row * HD + k] + g_c[CROWS + row * HD + k]
                + g_c[2 * CROWS + row * HD + k];
        s += fmaxf(c + b1s[k], 0.f) * W2s[k];
    }
    #pragma unroll
    for (int o = 16; o > 0; o >>= 1)
        s += __shfl_xor_sync(0xffffffffu, s, o);
    if (lane == 0)
        g_cand[row] = (s + b2s[0]) > THRESH ? 1 : 0;
}

// ---------------------------------------------------------------------------
// COMPACT: one block per batch. Builds row list + pair list.
// ---------------------------------------------------------------------------
__global__ void __launch_bounds__(SEQ) compact_kernel()
{
    __shared__ int fc[SEQ];
    const int b = blockIdx.x;
    const int t = threadIdx.x;
    fc[t] = g_cand[b * SEQ + t];
    __syncthreads();
    if (fc[t]) {
        int r = atomicAdd(&g_nrows, 1);
        g_rows[r] = b * SEQ + t;
        for (int j = 0; j < SEQ; j++) {
            if (fc[j] && j != t) {
                int p = atomicAdd(&g_cnt, 1);
                g_pairs[p] = (b * SEQ + t) * SEQ + j;   // rowi*256 + j
            }
        }
    }
}

// ---------------------------------------------------------------------------
// HAB: one WARP per (candidate row, output column). Max parallelism for the
// sparse case: g_nrows*1536 independent warp items, no smem, no serial loops.
// ---------------------------------------------------------------------------
__global__ void __launch_bounds__(256) hab_kernel(
    const float* __restrict__ X,
    const float* __restrict__ Wp1)
{
    const int lane   = threadIdx.x & 31;
    const int gwarp  = (blockIdx.x * 256 + threadIdx.x) >> 5;
    const int nwarps = gridDim.x * 8;
    const int total  = g_nrows * 1536;

    for (int item = gwarp; item < total; item += nwarps) {
        const int rs  = item / 1536;
        const int c   = item - rs * 1536;
        const int row = g_rows[rs];
        const float* xr = X + row * HD;
        const float* wrow = (c < HD) ? (Wp1 + (size_t)c * (2 * HD))
                                     : (Wp1 + (size_t)(c - HD) * (2 * HD) + HD);
        float s = 0.f;
        #pragma unroll
        for (int t = 0; t < HD / 32; t++) {
            int k = lane + 32 * t;
            s += __ldg(&xr[k]) * __ldg(&wrow[k]);
        }
        #pragma unroll
        for (int o = 16; o > 0; o >>= 1)
            s += __shfl_xor_sync(0xffffffffu, s, o);
        if (lane == 0) g_hab[(size_t)row * (2 * HD) + c] = s;
    }
}

// ---------------------------------------------------------------------------
// PAIR: one block per valid pair (grid-stride over g_cnt).
// out[b,i,j,:] = relu(ha_i + hb_j + bp1) @ Wp2^T + bp2
// ---------------------------------------------------------------------------
__global__ void __launch_bounds__(256) pair_kernel(
    const float* __restrict__ bp1,
    const float* __restrict__ Wp2,
    const float* __restrict__ bp2,
    float* __restrict__ out)
{
    __shared__ float v[HD];
    const int tid  = threadIdx.x;
    const int warp = tid >> 5;
    const int lane = tid & 31;
    const int cnt  = g_cnt;

    for (int p = blockIdx.x; p < cnt; p += gridDim.x) {
        int code = g_pairs[p];
        int rowi = code >> 8;
        int j    = code & 255;
        int rowj = (rowi & ~255) | j;

        __syncthreads();
        for (int k = tid; k < HD; k += 256)
            v[k] = fmaxf(g_hab[(size_t)rowi * (2 * HD) + k] +
                         g_hab[(size_t)rowj * (2 * HD) + HD + k] + bp1[k], 0.f);
        __syncthreads();

        float* o = out + (size_t)code * NP;
        for (int pp = warp; pp < NP; pp += 8) {
            float s = 0.f;
            #pragma unroll
            for (int t = 0; t < HD / 32; t++)
                s += v[lane + 32 * t] * __ldg(&Wp2[pp * HD + lane + 32 * t]);
            #pragma unroll
            for (int off = 16; off > 0; off >>= 1)
                s += __shfl_xor_sync(0xffffffffu, s, off);
            if (lane == 0) o[pp] = s + bp2[pp];
        }
    }
}

// ---------------------------------------------------------------------------
extern "C" void kernel_launch(void* const* d_in, const int* in_sizes, int n_in,
                              void* d_out, int out_size)
{
    const float* x   = (const float*)d_in[0];
    const float* W1s = (const float*)d_in[1];
    const float* b1s = (const float*)d_in[2];
    const float* W2s = (const float*)d_in[3];
    const float* b2s = (const float*)d_in[4];
    const float* Wp1 = (const float*)d_in[5];
    const float* bp1 = (const float*)d_in[6];
    const float* Wp2 = (const float*)d_in[7];
    const float* bp2 = (const float*)d_in[8];
    float* out = (float*)d_out;

    // 1) split-K partial GEMM + fused output zero-fill
    dim3 g1(HD / BN, ROWS / BM, 3);              // 288 CTAs, single wave
    gemm_kernel<<<g1, 256>>>(x, W1s, out);

    // 2) candidate mask (warp per row) + counter reset
    cand_kernel<<<ROWS / 8, 256>>>(b1s, W2s, b2s);

    // 3) build row + pair lists
    compact_kernel<<<BATCH, SEQ>>>();

    // 4) ha/hb: one warp per (row, col) — 15K independent items
    hab_kernel<<<1024, 256>>>(x, Wp1);

    // 5) one block per valid pair
    pair_kernel<<<1024, 256>>>(bp1, Wp2, bp2, out);
}

// round 9
// speedup vs baseline: 1.6631x; 1.0642x over previous
#include <cuda_runtime.h>

#define HD      768
#define SEQ     256
#define BATCH   4
#define ROWS    1024
#define NP      54
#define THRESH  0.5f
#define ROWOUT  (SEQ * NP)          // 13824
#define CROWS   (ROWS * HD)         // 786432 floats per split buffer

typedef unsigned long long u64;

// Scratch (device globals — no allocation allowed)
__device__ float g_c[3 * CROWS];         // split-K partials of x @ W1s^T (9.4 MB)
__device__ float g_hab[ROWS * 2 * HD];   // [row][ha | hb], candidate rows only
__device__ int   g_cand[ROWS];
__device__ int   g_rows[ROWS];
__device__ int   g_nrows;

__device__ __forceinline__ void fma2(u64& d, u64 a, u64 b) {
    asm("fma.rn.f32x2 %0, %1, %2, %0;" : "+l"(d) : "l"(a), "l"(b));
}
__device__ __forceinline__ u64 dup2(float a) {
    u64 r; asm("mov.b64 %0, {%1, %1};" : "=l"(r) : "f"(a)); return r;
}
__device__ __forceinline__ void unpack2(float& lo, float& hi, u64 v) {
    asm("mov.b64 {%0, %1}, %2;" : "=f"(lo), "=f"(hi) : "l"(v));
}

// ---------------------------------------------------------------------------
// GEMM: partial c = x[:, ks:ks+256] @ W1s[:, ks:ks+256]^T  -> g_c[split]
// BM=128, BN=64, BK=16, 256 threads, m-pair packed FFMA2, split-K = 3.
// Trickles the 56.6MB output zero-fill through the k-loop.
// ---------------------------------------------------------------------------
#define BM 128
#define BN 64
#define BK 16
#define KSPLIT 256
#define LDA 132
#define LDB 68

__global__ void __launch_bounds__(256, 2) gemm_kernel(
    const float* __restrict__ X,
    const float* __restrict__ W1s,
    float* __restrict__ out)
{
    __shared__ float As[2][BK * LDA];
    __shared__ float Bs[2][BK * LDB];

    const int tid = threadIdx.x;
    const int n0 = blockIdx.x * BN;
    const int m0 = blockIdx.y * BM;
    const int ks = blockIdx.z * KSPLIT;
    const int ty = tid >> 4;
    const int tx = tid & 15;

    const int ctaid = blockIdx.z * 96 + blockIdx.y * 12 + blockIdx.x;  // 0..287
    if (ctaid == 0 && tid == 0) g_nrows = 0;     // reset for later kernels
    float4* o4 = (float4*)out + ctaid * 12288 + tid;

    const int am  = tid >> 2;
    const int akq = (tid & 3) * 4;
    const int bn  = tid & 63;
    const int bkq = (tid >> 6) * 4;

    const float* gA0 = X + (m0 + am) * HD + ks + akq;
    const float* gA1 = gA0 + 64 * HD;
    const float* gB  = W1s + (n0 + bn) * HD + ks + bkq;

    u64 acc[4][4];
    #pragma unroll
    for (int j = 0; j < 4; j++)
        #pragma unroll
        for (int ip = 0; ip < 4; ip++) acc[j][ip] = 0ull;

    float4 ra0, ra1, rb;

    ra0 = *(const float4*)gA0;
    ra1 = *(const float4*)gA1;
    rb  = *(const float4*)gB;
    {
        As[0][(akq+0)*LDA + am]      = ra0.x;  As[0][(akq+1)*LDA + am]      = ra0.y;
        As[0][(akq+2)*LDA + am]      = ra0.z;  As[0][(akq+3)*LDA + am]      = ra0.w;
        As[0][(akq+0)*LDA + am + 64] = ra1.x;  As[0][(akq+1)*LDA + am + 64] = ra1.y;
        As[0][(akq+2)*LDA + am + 64] = ra1.z;  As[0][(akq+3)*LDA + am + 64] = ra1.w;
        Bs[0][(bkq+0)*LDB + bn] = rb.x;  Bs[0][(bkq+1)*LDB + bn] = rb.y;
        Bs[0][(bkq+2)*LDB + bn] = rb.z;  Bs[0][(bkq+3)*LDB + bn] = rb.w;
    }
    ra0 = *(const float4*)(gA0 + BK);
    ra1 = *(const float4*)(gA1 + BK);
    rb  = *(const float4*)(gB  + BK);

    const int NITER = KSPLIT / BK;   // 16
    const float4 z4 = make_float4(0.f, 0.f, 0.f, 0.f);

    for (int it = 0; it < NITER; it++) {
        __syncthreads();
        const int cb = it & 1;

        o4[(it * 3 + 0) * 256] = z4;
        o4[(it * 3 + 1) * 256] = z4;
        o4[(it * 3 + 2) * 256] = z4;

        #pragma unroll
        for (int k = 0; k < BK; k++) {
            ulonglong2 a01 = *(const ulonglong2*)&As[cb][k * LDA + ty * 8];
            ulonglong2 a23 = *(const ulonglong2*)&As[cb][k * LDA + ty * 8 + 4];
            float4 bf = *(const float4*)&Bs[cb][k * LDB + tx * 4];
            u64 ap[4] = {a01.x, a01.y, a23.x, a23.y};
            u64 bd[4] = {dup2(bf.x), dup2(bf.y), dup2(bf.z), dup2(bf.w)};
            #pragma unroll
            for (int j = 0; j < 4; j++)
                #pragma unroll
                for (int ip = 0; ip < 4; ip++)
                    fma2(acc[j][ip], ap[ip], bd[j]);
        }

        if (it + 1 < NITER) {
            const int sb = (it + 1) & 1;
            As[sb][(akq+0)*LDA + am]      = ra0.x;  As[sb][(akq+1)*LDA + am]      = ra0.y;
            As[sb][(akq+2)*LDA + am]      = ra0.z;  As[sb][(akq+3)*LDA + am]      = ra0.w;
            As[sb][(akq+0)*LDA + am + 64] = ra1.x;  As[sb][(akq+1)*LDA + am + 64] = ra1.y;
            As[sb][(akq+2)*LDA + am + 64] = ra1.z;  As[sb][(akq+3)*LDA + am + 64] = ra1.w;
            Bs[sb][(bkq+0)*LDB + bn] = rb.x;  Bs[sb][(bkq+1)*LDB + bn] = rb.y;
            Bs[sb][(bkq+2)*LDB + bn] = rb.z;  Bs[sb][(bkq+3)*LDB + bn] = rb.w;
            if (it + 2 < NITER) {
                int ko = (it + 2) * BK;
                ra0 = *(const float4*)(gA0 + ko);
                ra1 = *(const float4*)(gA1 + ko);
                rb  = *(const float4*)(gB  + ko);
            }
        }
    }

    float cv[8][4];
    #pragma unroll
    for (int j = 0; j < 4; j++)
        #pragma unroll
        for (int ip = 0; ip < 4; ip++)
            unpack2(cv[2*ip][j], cv[2*ip+1][j], acc[j][ip]);

    float* cb = g_c + blockIdx.z * CROWS;
    #pragma unroll
    for (int i = 0; i < 8; i++) {
        int m = m0 + ty * 8 + i;
        *(float4*)&cb[m * HD + n0 + tx * 4] =
            make_float4(cv[i][0], cv[i][1], cv[i][2], cv[i][3]);
    }
}

// ---------------------------------------------------------------------------
// CAND: warp per row: span = sum_n relu(c0+c1+c2 + b1s)*W2s[0] + b2s[0]
// Builds the candidate row list directly (order-invariant consumers).
// ---------------------------------------------------------------------------
__global__ void __launch_bounds__(256) cand_kernel(
    const float* __restrict__ b1s,
    const float* __restrict__ W2s,
    const float* __restrict__ b2s)
{
    const int row  = (blockIdx.x * 256 + threadIdx.x) >> 5;
    const int lane = threadIdx.x & 31;
    float s = 0.f;
    #pragma unroll
    for (int t = 0; t < HD / 32; t++) {
        int k = lane + 32 * t;
        float c = g_c[row * HD + k] + g_c[CROWS + row * HD + k]
                + g_c[2 * CROWS + row * HD + k];
        s += fmaxf(c + b1s[k], 0.f) * W2s[k];
    }
    #pragma unroll
    for (int o = 16; o > 0; o >>= 1)
        s += __shfl_xor_sync(0xffffffffu, s, o);
    if (lane == 0) {
        int c = (s + b2s[0]) > THRESH ? 1 : 0;
        g_cand[row] = c;
        if (c) {
            int r = atomicAdd(&g_nrows, 1);
            g_rows[r] = row;
        }
    }
}

// ---------------------------------------------------------------------------
// HAB: one WARP per (candidate row, 4-col group). x loaded once per warp,
// 4 independent dot accumulators -> 4x the MLP, 1/4 the x traffic.
// ---------------------------------------------------------------------------
__global__ void __launch_bounds__(256) hab_kernel(
    const float* __restrict__ X,
    const float* __restrict__ Wp1)
{
    const int lane   = threadIdx.x & 31;
    const int gwarp  = (blockIdx.x * 256 + threadIdx.x) >> 5;
    const int nwarps = gridDim.x * 8;
    const int total  = g_nrows * 384;           // 384 groups of 4 cols

    for (int item = gwarp; item < total; item += nwarps) {
        const int rs  = item / 384;
        const int c0  = (item - rs * 384) * 4;  // 0,4,...,1532
        const int row = g_rows[rs];
        const float* xr = X + row * HD;
        const float* wbase = (c0 < HD) ? (Wp1 + (size_t)c0 * (2 * HD))
                                       : (Wp1 + (size_t)(c0 - HD) * (2 * HD) + HD);
        float s0 = 0.f, s1 = 0.f, s2 = 0.f, s3 = 0.f;
        #pragma unroll
        for (int t = 0; t < HD / 32; t++) {
            int k = lane + 32 * t;
            float xv = __ldg(&xr[k]);
            s0 += xv * __ldg(&wbase[k]);
            s1 += xv * __ldg(&wbase[k + 2 * HD]);
            s2 += xv * __ldg(&wbase[k + 4 * HD]);
            s3 += xv * __ldg(&wbase[k + 6 * HD]);
        }
        #pragma unroll
        for (int o = 16; o > 0; o >>= 1) {
            s0 += __shfl_xor_sync(0xffffffffu, s0, o);
            s1 += __shfl_xor_sync(0xffffffffu, s1, o);
            s2 += __shfl_xor_sync(0xffffffffu, s2, o);
            s3 += __shfl_xor_sync(0xffffffffu, s3, o);
        }
        if (lane == 0)
            *(float4*)&g_hab[(size_t)row * (2 * HD) + c0] =
                make_float4(s0, s1, s2, s3);
    }
}

// ---------------------------------------------------------------------------
// PAIR: grid-stride blocks over (candidate slot, j). Uniform early-exit on
// invalid j; valid pairs compute relu(ha_i + hb_j + bp1) @ Wp2^T + bp2.
// ---------------------------------------------------------------------------
__global__ void __launch_bounds__(256) pair_kernel(
    const float* __restrict__ bp1,
    const float* __restrict__ Wp2,
    const float* __restrict__ bp2,
    float* __restrict__ out)
{
    __shared__ float v[HD];
    const int tid  = threadIdx.x;
    const int warp = tid >> 5;
    const int lane = tid & 31;
    const int total = g_nrows << 8;

    for (int it = blockIdx.x; it < total; it += gridDim.x) {
        const int slot = it >> 8;
        const int j    = it & 255;
        const int rowi = g_rows[slot];
        const int i    = rowi & 255;
        const int rowj = (rowi & ~255) | j;
        if (j == i || !g_cand[rowj]) continue;   // block-uniform

        __syncthreads();
        for (int k = tid; k < HD; k += 256)
            v[k] = fmaxf(g_hab[(size_t)rowi * (2 * HD) + k] +
                         g_hab[(size_t)rowj * (2 * HD) + HD + k] + bp1[k], 0.f);
        __syncthreads();

        float* o = out + ((size_t)rowi * SEQ + j) * NP;
        for (int pp = warp; pp < NP; pp += 8) {
            float s = 0.f;
            #pragma unroll
            for (int t = 0; t < HD / 32; t++)
                s += v[lane + 32 * t] * __ldg(&Wp2[pp * HD + lane + 32 * t]);
            #pragma unroll
            for (int off = 16; off > 0; off >>= 1)
                s += __shfl_xor_sync(0xffffffffu, s, off);
            if (lane == 0) o[pp] = s + bp2[pp];
        }
    }
}

// ---------------------------------------------------------------------------
extern "C" void kernel_launch(void* const* d_in, const int* in_sizes, int n_in,
                              void* d_out, int out_size)
{
    const float* x   = (const float*)d_in[0];
    const float* W1s = (const float*)d_in[1];
    const float* b1s = (const float*)d_in[2];
    const float* W2s = (const float*)d_in[3];
    const float* b2s = (const float*)d_in[4];
    const float* Wp1 = (const float*)d_in[5];
    const float* bp1 = (const float*)d_in[6];
    const float* Wp2 = (const float*)d_in[7];
    const float* bp2 = (const float*)d_in[8];
    float* out = (float*)d_out;

    // 1) split-K partial GEMM + fused output zero-fill + counter reset
    dim3 g1(HD / BN, ROWS / BM, 3);              // 288 CTAs, single wave
    gemm_kernel<<<g1, 256>>>(x, W1s, out);

    // 2) candidate mask + row list (warp per row)
    cand_kernel<<<ROWS / 8, 256>>>(b1s, W2s, b2s);

    // 3) ha/hb: one warp per (row, 4-col group)
    hab_kernel<<<512, 256>>>(x, Wp1);

    // 4) pair logits: grid-stride over (slot, j) with uniform early exit
    pair_kernel<<<2048, 256>>>(bp1, Wp2, bp2, out);
}